// round 10
// baseline (speedup 1.0000x reference)
#include <cuda_runtime.h>
#include <math.h>

// Problem shape (fixed by the dataset)
#define B_DIM 256
#define K_DIM 512
#define D_DIM 1024
#define RPU   4                              // rows per unit
#define UNIT_FLOATS (RPU * D_DIM)            // 4096 floats
#define UNIT_BYTES  (UNIT_FLOATS * 4)        // 16 KB, contiguous in bg_pro
#define NUNIT (B_DIM * K_DIM / RPU)          // 32768 units
#define GRID  592                            // 148 SMs x 4 resident blocks
#define NBIG  208                            // 208*56 + 384*55 = 32768
#define STAGES 3
#define INV_T 14.2857142857142857f           // 1/0.07

// dynamic smem layout
#define OFF_Q     0                          // float4 q_s[256]        (4096 B)
#define OFF_BUF   4096                       // float4 buf[3][1024]    (49152 B)
#define OFF_WRED  (4096 + STAGES * UNIT_BYTES)       // float w_red[16]
#define OFF_PRED  (OFF_WRED + 64)                    // float p_red[8]
#define OFF_SACC  (OFF_PRED + 32)                    // double sacc[4]
#define OFF_WPOS  (OFF_SACC + 32)                    // double w_pos[8]
#define OFF_WFG   (OFF_WPOS + 64)                    // double w_fg[8]
#define OFF_FLAG  (OFF_WFG + 64)                     // int flag
#define SMEM_BYTES (OFF_FLAG + 64)

// Scratch (no allocations). Fully overwritten each launch; ticket returns
// to 0 at the end of every launch (graph-replay safe).
__device__ double2      g_part[GRID];
__device__ unsigned int g_ticket;            // zero-initialized at module load

__global__ __launch_bounds__(256, 4)
void fused_kernel(const float* __restrict__ bg_img,
                  const float* __restrict__ fg_pro,
                  const float* __restrict__ bg_pro,
                  float* __restrict__ out) {
    extern __shared__ unsigned char smem_raw[];
    float4* q_s   = (float4*)(smem_raw + OFF_Q);
    float4* bufs  = (float4*)(smem_raw + OFF_BUF);
    float*  w_red = (float*) (smem_raw + OFF_WRED);
    float*  p_red = (float*) (smem_raw + OFF_PRED);
    double* sacc  = (double*)(smem_raw + OFF_SACC);
    double* w_pos = (double*)(smem_raw + OFF_WPOS);
    double* w_fg  = (double*)(smem_raw + OFF_WFG);
    int*    s_fl  = (int*)   (smem_raw + OFF_FLAG);

    const int tid  = threadIdx.x;
    const int warp = tid >> 5;
    const int lane = tid & 31;
    const int bid  = blockIdx.x;

    // static contiguous chunk of units
    const int lo = (bid < NBIG) ? bid * 56 : NBIG * 56 + (bid - NBIG) * 55;
    const int hi = lo + ((bid < NBIG) ? 56 : 55);

    double acc = 0.0, fg_acc = 0.0;
    float  scale = 0.f;
    int    cur_b = -1;

    const unsigned sbuf0 = (unsigned)__cvta_generic_to_shared(bufs);

    // issue one 16KB unit via 4x cp.async.cg(16B) per thread; always commit
    auto issue_unit = [&](int u, int st) {
        if (u < hi) {
            const float* src = bg_pro + (size_t)u * UNIT_FLOATS + tid * 4;
            unsigned dst = sbuf0 + (unsigned)st * UNIT_BYTES + tid * 16;
            #pragma unroll
            for (int j = 0; j < 4; j++) {
                asm volatile("cp.async.cg.shared.global [%0], [%1], 16;\n"
                             :: "r"(dst + j * 4096), "l"(src + j * 1024)
                             : "memory");
            }
        }
        asm volatile("cp.async.commit_group;\n" ::: "memory");
    };

    // prologue: fill the 3-deep ring
    issue_unit(lo + 0, 0);
    issue_unit(lo + 1, 1);
    issue_unit(lo + 2, 2);

    for (int u = lo; u < hi; u++) {
        const int st = (u - lo) % 3;
        const int r0 = u * RPU;
        const int b  = r0 >> 9;              // row / 512
        const int k0 = r0 & 511;

        if (b != cur_b) {
            // per-b setup overlaps in-flight cp.asyncs
            const float4* qrow = (const float4*)(bg_img + (size_t)b * D_DIM);
            float4 qv = qrow[tid];
            float ss = qv.x*qv.x + qv.y*qv.y + qv.z*qv.z + qv.w*qv.w;
            float fd = 0.f;
            if (k0 == 0) {                   // this block owns b's fg term
                const float4* frow = (const float4*)(fg_pro + (size_t)b * D_DIM);
                float4 f = frow[tid];
                fd = qv.x*f.x + qv.y*f.y + qv.z*f.z + qv.w*f.w;
            }
            #pragma unroll
            for (int o = 16; o; o >>= 1) {
                ss += __shfl_xor_sync(0xFFFFFFFFu, ss, o);
                fd += __shfl_xor_sync(0xFFFFFFFFu, fd, o);
            }
            if (lane == 0) { w_red[warp] = ss; w_red[8 + warp] = fd; }
            q_s[tid] = qv;                   // raw (unnormalized)
            __syncthreads();
            float tss = 0.f;
            #pragma unroll
            for (int i = 0; i < 8; i++) tss += w_red[i];
            const float inv = 1.0f / sqrtf(tss);
            scale = inv * INV_T;
            if (tid == 0 && k0 == 0) {
                float tfd = 0.f;
                #pragma unroll
                for (int i = 0; i < 8; i++) tfd += w_red[8 + i];
                fg_acc += (double)expf(tfd * inv * INV_T);
            }
            cur_b = b;
        }

        // oldest stage complete (2 groups may stay pending)
        asm volatile("cp.async.wait_group 2;\n" ::: "memory");
        __syncthreads();

        // compute: 2 warps per row; warp covers 2KB = 128 float4
        {
            const float4* rb = bufs + st * 1024 + (warp >> 1) * 256 + (warp & 1) * 128;
            const float4* qb = q_s + (warp & 1) * 128;
            float s = 0.f;
            #pragma unroll
            for (int i = 0; i < 4; i++) {
                const int idx = i * 32 + lane;
                float4 a  = rb[idx];
                float4 qv = qb[idx];
                s = fmaf(qv.x, a.x, s);
                s = fmaf(qv.y, a.y, s);
                s = fmaf(qv.z, a.z, s);
                s = fmaf(qv.w, a.w, s);
            }
            #pragma unroll
            for (int o = 16; o; o >>= 1) s += __shfl_xor_sync(0xFFFFFFFFu, s, o);
            if (lane == 0) p_red[warp] = s;
        }
        __syncthreads();   // p_red visible; buf[st] free to refill

        if (tid < 4)       // row r logit = p[2r] + p[2r+1]
            acc += (double)expf((p_red[2 * tid] + p_red[2 * tid + 1]) * scale);

        issue_unit(u + 3, st);
    }
    asm volatile("cp.async.wait_group 0;\n" ::: "memory");

    // ---- block partial + ticketed last-block finish ----
    __syncthreads();
    if (tid < 4) sacc[tid] = acc;
    __syncthreads();

    if (tid == 0) {
        double t = sacc[0] + sacc[1] + sacc[2] + sacc[3];
        g_part[bid] = make_double2(t, fg_acc);
        __threadfence();
        unsigned int done = atomicAdd(&g_ticket, 1u);
        *s_fl = (done == (unsigned int)(GRID - 1)) ? 1 : 0;
    }
    __syncthreads();

    if (*s_fl) {
        const volatile double* vp = reinterpret_cast<const volatile double*>(g_part);
        double pos = 0.0, fg = 0.0;
        for (int i = tid; i < GRID; i += 256) {
            pos += vp[2 * i + 0];
            fg  += vp[2 * i + 1];
        }
        #pragma unroll
        for (int o = 16; o; o >>= 1) {
            pos += __shfl_xor_sync(0xFFFFFFFFu, pos, o);
            fg  += __shfl_xor_sync(0xFFFFFFFFu, fg,  o);
        }
        if (lane == 0) { w_pos[warp] = pos; w_fg[warp] = fg; }
        __syncthreads();
        if (tid == 0) {
            double P = 0.0, F = 0.0;
            #pragma unroll
            for (int i = 0; i < 8; i++) { P += w_pos[i]; F += w_fg[i]; }
            // -log(pos/neg) = log1p(K * F / S)
            out[0] = (float)log1p(F * (double)K_DIM / P);
            g_ticket = 0;   // restore for next graph replay
        }
    }
}

extern "C" void kernel_launch(void* const* d_in, const int* in_sizes, int n_in,
                              void* d_out, int out_size) {
    const float* bg_img = (const float*)d_in[0];   // [B, D]
    const float* fg_pro = (const float*)d_in[1];   // [B, D]
    const float* bg_pro = (const float*)d_in[2];   // [B, K, D]
    float* out = (float*)d_out;

    cudaFuncSetAttribute(fused_kernel,
                         cudaFuncAttributeMaxDynamicSharedMemorySize, SMEM_BYTES);
    fused_kernel<<<GRID, 256, SMEM_BYTES>>>(bg_img, fg_pro, bg_pro, out);
}

// round 11
// speedup vs baseline: 1.0113x; 1.0113x over previous
#include <cuda_runtime.h>
#include <math.h>

// Problem shape (fixed by the dataset)
#define B_DIM 256
#define K_DIM 512
#define D_DIM 1024
#define KPB   64                      // k rows per tile (16 warps x 4 rows)
#define KYN   (K_DIM / KPB)           // 8 tiles per batch row
#define NTILE (B_DIM * KYN)           // 2048 tiles
#define GRID  296                     // 148 SMs x 2 resident blocks
#define NBIG  272                     // 272*7 + 24*6 = 2048
#define NTHR  512
#define INV_T 14.2857142857142857f    // 1/0.07

// Scratch (no allocations). Fully overwritten each launch; ticket returns
// to 0 at the end of every launch (graph-replay safe).
__device__ double2      g_part[GRID];
__device__ unsigned int g_ticket;      // zero-initialized at module load

// dynamic smem: q row (4KB) + reductions + ~80KB total ballast to pin
// exactly 2 blocks/SM (228KB / 80KB = 2.85 -> 2 resident).
#define SMEM_BYTES (80 * 1024)
#define OFF_Q     0                    // float q[1024]      (4096 B)
#define OFF_WRED  4096                 // float w_red[32]
#define OFF_SACC  (4096 + 128)         // double sacc[16]
#define OFF_WPOS  (OFF_SACC + 128)     // double w_pos[16]
#define OFF_WFG   (OFF_WPOS + 128)     // double w_fg[16]
#define OFF_FLAG  (OFF_WFG + 128)      // int flag

__global__ __launch_bounds__(NTHR, 2)
void fused_kernel(const float* __restrict__ bg_img,
                  const float* __restrict__ fg_pro,
                  const float* __restrict__ bg_pro,
                  float* __restrict__ out) {
    extern __shared__ unsigned char smem_raw[];
    float2* q_s2  = (float2*)(smem_raw + OFF_Q);     // 512 x float2 view
    float4* q_s4  = (float4*)(smem_raw + OFF_Q);     // 256 x float4 view
    float*  w_red = (float*) (smem_raw + OFF_WRED);  // 16 ss + 16 fd
    double* sacc  = (double*)(smem_raw + OFF_SACC);
    double* w_pos = (double*)(smem_raw + OFF_WPOS);
    double* w_fg  = (double*)(smem_raw + OFF_WFG);
    int*    s_fl  = (int*)   (smem_raw + OFF_FLAG);

    const int tid  = threadIdx.x;
    const int warp = tid >> 5;        // 0..15
    const int lane = tid & 31;
    const int bid  = blockIdx.x;

    // static contiguous chunk of tiles
    const int lo = (bid < NBIG) ? bid * 7 : NBIG * 7 + (bid - NBIG) * 6;
    const int hi = lo + ((bid < NBIG) ? 7 : 6);

    double acc_lane = 0.0;   // per-lane running sum of exp(bg_logit/T)
    double fg_acc   = 0.0;   // meaningful on tid 0 only
    float  scale    = 0.f;   // inv_norm(b) * INV_T, cached per b
    int    cur_b    = -1;

    for (int t = lo; t < hi; t++) {
        const int b  = t >> 3;          // t / KYN
        const int ky = t & (KYN - 1);   // t % KYN

        if (b != cur_b) {
            // ---- per-b setup: publish RAW q row, reduce sumsq (+fg dot) ----
            __syncthreads();   // previous tile's readers of q_s are done

            const float2* qrow = (const float2*)(bg_img + (size_t)b * D_DIM);
            float2 qv = qrow[tid];
            float ss = qv.x*qv.x + qv.y*qv.y;

            float fd = 0.f;
            if (ky == 0) {     // this block owns b's fg tile
                const float2* frow = (const float2*)(fg_pro + (size_t)b * D_DIM);
                float2 f = frow[tid];
                fd = qv.x*f.x + qv.y*f.y;
            }
            #pragma unroll
            for (int o = 16; o; o >>= 1) {
                ss += __shfl_xor_sync(0xFFFFFFFFu, ss, o);
                fd += __shfl_xor_sync(0xFFFFFFFFu, fd, o);
            }
            if (lane == 0) { w_red[warp] = ss; w_red[16 + warp] = fd; }
            q_s2[tid] = qv;                      // raw (unnormalized)
            __syncthreads();                     // q_s + w_red visible

            float tss = 0.f;
            #pragma unroll
            for (int i = 0; i < 16; i++) tss += w_red[i];
            const float inv = 1.0f / sqrtf(tss);
            scale = inv * INV_T;

            if (tid == 0 && ky == 0) {
                float tfd = 0.f;
                #pragma unroll
                for (int i = 0; i < 16; i++) tfd += w_red[16 + i];
                fg_acc += (double)expf(tfd * inv * INV_T);
            }
            cur_b = b;
        }
        // (b unchanged: no sync — loads overlap previous tile's tail)

        // ---- hot loop: warp owns 4 k rows; pure LDG/LDS/FFMA ----
        const int k0 = ky * KPB + warp * 4;
        const float* pbase = bg_pro + ((size_t)b * K_DIM + k0) * D_DIM;
        const float4* p0 = (const float4*)(pbase + (size_t)0 * D_DIM);
        const float4* p1 = (const float4*)(pbase + (size_t)1 * D_DIM);
        const float4* p2 = (const float4*)(pbase + (size_t)2 * D_DIM);
        const float4* p3 = (const float4*)(pbase + (size_t)3 * D_DIM);

        float s0 = 0.f, s1 = 0.f, s2 = 0.f, s3 = 0.f;
        #pragma unroll
        for (int i = 0; i < 8; i++) {
            const int idx = i * 32 + lane;
            float4 qi = q_s4[idx];
            float4 a0 = __ldcs(&p0[idx]);
            float4 a1 = __ldcs(&p1[idx]);
            float4 a2 = __ldcs(&p2[idx]);
            float4 a3 = __ldcs(&p3[idx]);
            s0 = fmaf(qi.x, a0.x, s0); s0 = fmaf(qi.y, a0.y, s0);
            s0 = fmaf(qi.z, a0.z, s0); s0 = fmaf(qi.w, a0.w, s0);
            s1 = fmaf(qi.x, a1.x, s1); s1 = fmaf(qi.y, a1.y, s1);
            s1 = fmaf(qi.z, a1.z, s1); s1 = fmaf(qi.w, a1.w, s1);
            s2 = fmaf(qi.x, a2.x, s2); s2 = fmaf(qi.y, a2.y, s2);
            s2 = fmaf(qi.z, a2.z, s2); s2 = fmaf(qi.w, a2.w, s2);
            s3 = fmaf(qi.x, a3.x, s3); s3 = fmaf(qi.y, a3.y, s3);
            s3 = fmaf(qi.z, a3.z, s3); s3 = fmaf(qi.w, a3.w, s3);
        }

        // ---- tail: 4 shfl trees; inv applied at the exponent ----
        float r;
        r = s0;
        #pragma unroll
        for (int o = 16; o; o >>= 1) r += __shfl_xor_sync(0xFFFFFFFFu, r, o);
        if (lane == 0) acc_lane += (double)expf(r * scale);
        r = s1;
        #pragma unroll
        for (int o = 16; o; o >>= 1) r += __shfl_xor_sync(0xFFFFFFFFu, r, o);
        if (lane == 1) acc_lane += (double)expf(r * scale);
        r = s2;
        #pragma unroll
        for (int o = 16; o; o >>= 1) r += __shfl_xor_sync(0xFFFFFFFFu, r, o);
        if (lane == 2) acc_lane += (double)expf(r * scale);
        r = s3;
        #pragma unroll
        for (int o = 16; o; o >>= 1) r += __shfl_xor_sync(0xFFFFFFFFu, r, o);
        if (lane == 3) acc_lane += (double)expf(r * scale);
    }

    // ---- once-per-block reduction + ticketed finish ----
    #pragma unroll
    for (int o = 16; o; o >>= 1)
        acc_lane += __shfl_xor_sync(0xFFFFFFFFu, acc_lane, o);
    __syncthreads();
    if (lane == 0) sacc[warp] = acc_lane;
    __syncthreads();

    if (tid == 0) {
        double tsum = 0.0;
        #pragma unroll
        for (int i = 0; i < 16; i++) tsum += sacc[i];
        g_part[bid] = make_double2(tsum, fg_acc);
        __threadfence();
        unsigned int done = atomicAdd(&g_ticket, 1u);
        *s_fl = (done == (unsigned int)(GRID - 1)) ? 1 : 0;
    }
    __syncthreads();

    if (*s_fl) {
        const volatile double* vp = reinterpret_cast<const volatile double*>(g_part);
        double pos = 0.0, fg = 0.0;
        for (int i = tid; i < GRID; i += NTHR) {
            pos += vp[2 * i + 0];
            fg  += vp[2 * i + 1];
        }
        #pragma unroll
        for (int o = 16; o; o >>= 1) {
            pos += __shfl_xor_sync(0xFFFFFFFFu, pos, o);
            fg  += __shfl_xor_sync(0xFFFFFFFFu, fg,  o);
        }
        if (lane == 0) { w_pos[warp] = pos; w_fg[warp] = fg; }
        __syncthreads();
        if (tid == 0) {
            double P = 0.0, F = 0.0;
            #pragma unroll
            for (int i = 0; i < 16; i++) { P += w_pos[i]; F += w_fg[i]; }
            // -log(pos/neg) = log1p(K * F / S)
            out[0] = (float)log1p(F * (double)K_DIM / P);
            g_ticket = 0;   // restore for next graph replay
        }
    }
}

extern "C" void kernel_launch(void* const* d_in, const int* in_sizes, int n_in,
                              void* d_out, int out_size) {
    const float* bg_img = (const float*)d_in[0];   // [B, D]
    const float* fg_pro = (const float*)d_in[1];   // [B, D]
    const float* bg_pro = (const float*)d_in[2];   // [B, K, D]
    float* out = (float*)d_out;

    cudaFuncSetAttribute(fused_kernel,
                         cudaFuncAttributeMaxDynamicSharedMemorySize, SMEM_BYTES);
    fused_kernel<<<GRID, NTHR, SMEM_BYTES>>>(bg_img, fg_pro, bg_pro, out);
}